// round 12
// baseline (speedup 1.0000x reference)
#include <cuda_runtime.h>
#include <math.h>

#define NB 4
#define NS 256
#define ND 300
#define NM (NB*NS)   // 1024 rows
#define NK 300
#define N3 (3*ND)    // 900: (spare) | ph | g1(+b_f)
#define CC 5.0f
#define IG 2

// weight: exp(C*tanh(x/C)) = e^C * 2^(K2/(1 + 2^(x*K_PRE))); e^C cancels in softmax
#define K_PRE 0.5770780163555854f     //  2*log2(e)/C
#define K2   -14.426950408889634f     // -2*C*log2(e)
#define LOG2E 1.4426950408889634f

// Scratch (static device globals — no allocation allowed)
__device__ float  g_rep[NM*ND];
__device__ float2 g_pr[NM*ND];        // (.x = pd = 2^(dep*K_PRE), .y = rep)
__device__ float  g_dhg[NM*N3];
__device__ float  g_attn[NM*ND];
__device__ float  g_p0[NM*ND];
__device__ float  g_p1[NM*ND];
__device__ float  g_p2[NM*ND];

#define BM 64
#define BN 64
#define BK 20        // 300 = 15 * 20; split-K3: 5 iters each
#define LPT 5        // loads/thread/tile: 64*20/256
#define APAD 2       // As row stride BM+2 ulls = 528B: 16B-aligned, bank-spread

typedef unsigned long long ull;

// ---------------- packed f32x2 helpers (FFMA2: 2x fp32 FMA rate) ------------
__device__ __forceinline__ ull pack2(float x, float y){
    ull r; asm("mov.b64 %0, {%1,%2};" : "=l"(r) : "f"(x), "f"(y)); return r;
}
__device__ __forceinline__ void ffma2(ull& d, ull a, ull b){
    asm("fma.rn.f32x2 %0, %1, %2, %0;" : "+l"(d) : "l"(a), "l"(b));
}
__device__ __forceinline__ float2 unpk(ull v){
    float2 r; asm("mov.b64 {%0,%1}, %2;" : "=f"(r.x), "=f"(r.y) : "l"(v)); return r;
}
__device__ __forceinline__ float ex2a(float x){ float y; asm("ex2.approx.f32 %0,%1;" : "=f"(y):"f"(x)); return y; }
__device__ __forceinline__ float rcpa(float x){ float y; asm("rcp.approx.f32 %0,%1;" : "=f"(y):"f"(x)); return y; }

// weight from precomputed pd=2^(dep'), ph=2^(head'): 4 instr, 2 MUFU
__device__ __forceinline__ float wfun2(float pd, float ph)
{
    float r = rcpa(fmaf(pd, ph, 1.f));
    return ex2a(K2 * r);
}

// 64x64 tile GEMM, C[m,n] += A[m,k]*W[n,k]. Double-buffered smem.
// A-tile stored DUPLICATED-PACKED f32x2 with 528B row stride (16B-aligned,
// <=3-way store bank conflicts). Inner k-step: 3x LDS.128 + 8x FFMA2.
__device__ __forceinline__ void gemm_core(const float* __restrict__ A,
                                          const float* __restrict__ W,
                                          int m0, int n0, int kstart, int niter,
                                          ull (&acc)[4][2])
{
    __shared__ __align__(16) ull   As[2][BK][BM+APAD];
    __shared__ __align__(16) float Bs[2][BK][BN+4];
    const int tid = threadIdx.x;
    const int tx = tid & 15, ty = tid >> 4;

    #pragma unroll
    for (int e = 0; e < LPT; ++e) {
        int idx = tid + e*256;
        int r = idx / BK, c = idx - r*BK;
        float va = A[(m0 + r)*NK + kstart + c];
        As[0][c][r] = pack2(va, va);
        int gn = n0 + r;
        Bs[0][c][r] = (gn < ND) ? W[gn*NK + kstart + c] : 0.f;
    }
    __syncthreads();

    int buf = 0;
    for (int it = 0; it < niter; ++it) {
        const bool has_next = (it + 1 < niter);
        float ra[LPT], rb[LPT];
        if (has_next) {
            int kn = kstart + (it + 1)*BK;
            #pragma unroll
            for (int e = 0; e < LPT; ++e) {
                int idx = tid + e*256;
                int r = idx / BK, c = idx - r*BK;
                ra[e] = A[(m0 + r)*NK + kn + c];
                int gn = n0 + r;
                rb[e] = (gn < ND) ? W[gn*NK + kn + c] : 0.f;
            }
        }
        #pragma unroll
        for (int k = 0; k < BK; ++k) {
            const ull* ap = &As[buf][k][ty*4];
            const ulonglong2 a01 = *(const ulonglong2*)ap;
            const ulonglong2 a23 = *(const ulonglong2*)(ap + 2);
            const ulonglong2 bb  = *(const ulonglong2*)&Bs[buf][k][tx*4];
            ffma2(acc[0][0], a01.x, bb.x); ffma2(acc[0][1], a01.x, bb.y);
            ffma2(acc[1][0], a01.y, bb.x); ffma2(acc[1][1], a01.y, bb.y);
            ffma2(acc[2][0], a23.x, bb.x); ffma2(acc[2][1], a23.x, bb.y);
            ffma2(acc[3][0], a23.y, bb.x); ffma2(acc[3][1], a23.y, bb.y);
        }
        if (has_next) {
            __syncthreads();
            #pragma unroll
            for (int e = 0; e < LPT; ++e) {
                int idx = tid + e*256;
                int r = idx / BK, c = idx - r*BK;
                As[buf^1][c][r] = pack2(ra[e], ra[e]);
                Bs[buf^1][c][r] = rb[e];
            }
            __syncthreads();
            buf ^= 1;
        }
    }
}

__device__ __forceinline__ void store_partial(float* __restrict__ dst,
                                              ull (&acc)[4][2], int m0, int n0)
{
    const int tx = threadIdx.x & 15, ty = threadIdx.x >> 4;
    #pragma unroll
    for (int p = 0; p < 4; ++p) {
        int m = m0 + ty*4 + p;
        #pragma unroll
        for (int qq = 0; qq < 2; ++qq) {
            float2 v = unpk(acc[p][qq]);
            int n = n0 + tx*4 + qq*2;
            if (n < ND)     dst[m*ND + n]     = v.x;
            if (n + 1 < ND) dst[m*ND + n + 1] = v.y;
        }
    }
}

// ---- P1: rep partial GEMM, split-K3 (z: k in [100z, 100z+100), 5 iters) ----
__global__ void __launch_bounds__(256)
gemm_rep_split(const float* __restrict__ A, const float* __restrict__ W)
{
    const int m0 = blockIdx.y * BM, n0 = blockIdx.x * BN;
    const int z = blockIdx.z;
    float* __restrict__ dst = (z == 0) ? g_p0 : ((z == 1) ? g_p1 : g_p2);
    ull acc[4][2] = {};
    gemm_core(A, W, m0, n0, z*100, 5, acc);
    store_partial(dst, acc, m0, n0);
}

// ---- P1b: g_rep = elu(p0 + p1 + p2 + b_fc); also fills g_pr.y --------------
__global__ void __launch_bounds__(256)
finish_rep(const float* __restrict__ bias)
{
    int idx = blockIdx.x * 256 + threadIdx.x;
    if (idx >= NM*ND) return;
    int n = idx % ND;
    float v = g_p0[idx] + g_p1[idx] + g_p2[idx] + bias[n];
    float r = (v > 0.f) ? v : expm1f(v);
    g_rep[idx] = r;
    g_pr[idx].y = r;
}

// ---- P2: pd/ph/gate1 GEMM (z: 0->g_pr.x (pd), 1->ph, 2->g1) ----------------
__global__ void __launch_bounds__(256)
gemm_triple(const float* __restrict__ W1, const float* __restrict__ W2,
            const float* __restrict__ Wf1, const float* __restrict__ b1,
            const float* __restrict__ bf)
{
    const int m0 = blockIdx.y * BM, n0 = blockIdx.x * BN;
    const int z = blockIdx.z;
    const float* W = (z == 0) ? W1 : ((z == 1) ? W2 : Wf1);
    ull acc[4][2] = {};
    gemm_core(g_rep, W, m0, n0, 0, 15, acc);
    const int tx = threadIdx.x & 15, ty = threadIdx.x >> 4;
    #pragma unroll
    for (int p = 0; p < 4; ++p) {
        int m = m0 + ty*4 + p;
        #pragma unroll
        for (int qq = 0; qq < 2; ++qq) {
            float2 v = unpk(acc[p][qq]);
            int n = n0 + tx*4 + qq*2;
            #pragma unroll
            for (int h = 0; h < 2; ++h) {
                int nn = n + h;
                if (nn < ND) {
                    float val = (h == 0) ? v.x : v.y;
                    if (z == 0) {
                        g_pr[m*ND + nn].x = ex2a(val * K_PRE);                 // pd
                    } else if (z == 1) {
                        g_dhg[m*N3 + ND + nn] = ex2a((val + b1[nn]) * K_PRE);  // ph
                    } else {
                        g_dhg[m*N3 + 2*ND + nn] = val + bf[nn];                // g1
                    }
                }
            }
        }
    }
}

// ---- P3: attention (IG=2, 320 thr, float2 loads, j x4, software-pipelined) -
__global__ void __launch_bounds__(320)
attn_kernel(const int* __restrict__ rmask)
{
    const int b = blockIdx.y;
    const int i0 = blockIdx.x * IG;
    const int t = threadIdx.x;

    __shared__ __align__(16) int joff[NS];   // j*(ND*8): byte offset into g_pr
    __shared__ int wcnt[8];
    __shared__ int nvalid_s;
    __shared__ int jfirst_s;

    bool v = false;
    unsigned bal = 0;
    if (t < NS) {
        v = (t > i0) && (rmask[b*NS + t] != 0);
        bal = __ballot_sync(0xFFFFFFFFu, v);
        if ((t & 31) == 0) wcnt[t >> 5] = __popc(bal);
    }
    __syncthreads();
    if (t == 0) {
        int a = 0;
        #pragma unroll
        for (int k = 0; k < 8; ++k) { int c = wcnt[k]; wcnt[k] = a; a += c; }
        nvalid_s = a;
    }
    __syncthreads();
    if (t < NS && v) {
        int pos = wcnt[t >> 5] + __popc(bal & ((1u << (t & 31)) - 1u));
        joff[pos] = t * (ND*8);
        if (pos == 0) jfirst_s = t;
    }
    __syncthreads();

    const int nvalid = nvalid_s;
    if (t >= ND) return;

    const float ph0 = g_dhg[(size_t)(b*NS + i0    )*N3 + ND + t];
    const float ph1 = g_dhg[(size_t)(b*NS + i0 + 1)*N3 + ND + t];
    const char* __restrict__ prp = (const char*)(g_pr + (size_t)(b*NS)*ND + t);

    float s0 = 0.f, w0 = 0.f, s1 = 0.f, w1 = 0.f;
    const int nvalid4 = nvalid & ~3;

    // software pipeline: group k+1's float2 loads issued before group k's use
    float2 prc[4];
    if (nvalid4 > 0) {
        const int4 o = *(const int4*)&joff[0];
        prc[0] = *(const float2*)(prp + o.x);
        prc[1] = *(const float2*)(prp + o.y);
        prc[2] = *(const float2*)(prp + o.z);
        prc[3] = *(const float2*)(prp + o.w);
    }
    for (int idx = 0; idx < nvalid4; idx += 4) {
        float2 prn[4];
        const bool hn = (idx + 4) < nvalid4;
        if (hn) {
            const int4 o = *(const int4*)&joff[idx + 4];
            prn[0] = *(const float2*)(prp + o.x);
            prn[1] = *(const float2*)(prp + o.y);
            prn[2] = *(const float2*)(prp + o.z);
            prn[3] = *(const float2*)(prp + o.w);
        }
        float e00 = wfun2(prc[0].x, ph0), e10 = wfun2(prc[0].x, ph1);
        float e01 = wfun2(prc[1].x, ph0), e11 = wfun2(prc[1].x, ph1);
        float e02 = wfun2(prc[2].x, ph0), e12 = wfun2(prc[2].x, ph1);
        float e03 = wfun2(prc[3].x, ph0), e13 = wfun2(prc[3].x, ph1);
        s0 += (e00 + e01) + (e02 + e03);
        s1 += (e10 + e11) + (e12 + e13);
        w0 = fmaf(e00, prc[0].y, fmaf(e01, prc[1].y, fmaf(e02, prc[2].y, fmaf(e03, prc[3].y, w0))));
        w1 = fmaf(e10, prc[0].y, fmaf(e11, prc[1].y, fmaf(e12, prc[2].y, fmaf(e13, prc[3].y, w1))));
        if (hn) {
            #pragma unroll
            for (int q = 0; q < 4; ++q) prc[q] = prn[q];
        }
    }
    for (int idx = nvalid4; idx < nvalid; ++idx) {
        float2 pr = *(const float2*)(prp + joff[idx]);
        float e0 = wfun2(pr.x, ph0), e1 = wfun2(pr.x, ph1);
        s0 += e0;  w0 = fmaf(e0, pr.y, w0);
        s1 += e1;  w1 = fmaf(e1, pr.y, w1);
    }
    // i1 = i0+1 must exclude j == i0+1 (only possibly-invalid entry = first);
    // exact cancellation: identical op sequence both times.
    if (nvalid > 0 && jfirst_s == i0 + 1) {
        float2 pr = *(const float2*)(prp + (i0 + 1)*(ND*8));
        float e1 = wfun2(pr.x, ph1);
        s1 -= e1;  w1 = fmaf(-e1, pr.y, w1);
    }
    float d0 = s0 + ((s0 == 0.f) ? 1.f : 0.f) + 1e-20f;
    float d1 = s1 + ((s1 == 0.f) ? 1.f : 0.f) + 1e-20f;
    g_attn[(size_t)(b*NS + i0    )*ND + t] = __fdividef(w0, d0);
    g_attn[(size_t)(b*NS + i0 + 1)*ND + t] = __fdividef(w1, d1);
}

// ---- P4: attn @ W_f2^T, split-K3 partials ----------------------------------
__global__ void __launch_bounds__(256)
gemm_final_split(const float* __restrict__ Wf2)
{
    const int m0 = blockIdx.y * BM, n0 = blockIdx.x * BN;
    const int z = blockIdx.z;
    float* __restrict__ dst = (z == 0) ? g_p0 : ((z == 1) ? g_p1 : g_p2);
    ull acc[4][2] = {};
    gemm_core(g_attn, Wf2, m0, n0, z*100, 5, acc);
    store_partial(dst, acc, m0, n0);
}

// ---- P4b: gate + blend + mask ----------------------------------------------
__global__ void __launch_bounds__(256)
final_epi(const int* __restrict__ rmask, float* __restrict__ out)
{
    int idx = blockIdx.x * 256 + threadIdx.x;
    if (idx >= NM*ND) return;
    int m = idx / ND, n = idx - m*ND;
    float vv = g_p0[idx] + g_p1[idx] + g_p2[idx] + g_dhg[m*N3 + 2*ND + n];
    float gate = rcpa(1.f + ex2a(-vv * LOG2E));
    float r = g_rep[idx];
    float a = g_attn[idx];
    out[idx] = (gate*r + (1.f - gate)*a) * (float)rmask[m];
}

extern "C" void kernel_launch(void* const* d_in, const int* in_sizes, int n_in,
                              void* d_out, int out_size)
{
    const float* inputs = (const float*)d_in[0];
    const int*   rmask  = (const int*)d_in[1];
    const float* W_fc   = (const float*)d_in[2];
    const float* b_fc   = (const float*)d_in[3];
    const float* W1     = (const float*)d_in[4];
    const float* W2     = (const float*)d_in[5];
    const float* b1     = (const float*)d_in[6];
    const float* W_f1   = (const float*)d_in[7];
    const float* W_f2   = (const float*)d_in[8];
    const float* b_f    = (const float*)d_in[9];
    float* out = (float*)d_out;

    dim3 blk(256);
    const int eBlocks = (NM*ND + 255) / 256;

    gemm_rep_split  <<<dim3(5, 16, 3), blk>>>(inputs, W_fc);
    finish_rep      <<<eBlocks, blk>>>(b_fc);
    gemm_triple     <<<dim3(5, 16, 3), blk>>>(W1, W2, W_f1, b1, b_f);
    attn_kernel     <<<dim3(NS/IG, NB), 320>>>(rmask);
    gemm_final_split<<<dim3(5, 16, 3), blk>>>(W_f2);
    final_epi       <<<eBlocks, blk>>>(rmask, out);
}

// round 13
// speedup vs baseline: 1.0762x; 1.0762x over previous
#include <cuda_runtime.h>
#include <math.h>

#define NB 4
#define NS 256
#define ND 300
#define NM (NB*NS)   // 1024 rows
#define NK 300
#define N3 (3*ND)    // 900: pd | ph | g1(+b_f)
#define CC 5.0f
#define IG 2

// weight: exp(C*tanh(x/C)) = e^C * 2^(K2/(1 + 2^(x*K_PRE))); e^C cancels in softmax
#define K_PRE 0.5770780163555854f     //  2*log2(e)/C
#define K2   -14.426950408889634f     // -2*C*log2(e)
#define LOG2E 1.4426950408889634f

// Scratch (static device globals — no allocation allowed)
__device__ float g_rep[NM*ND];
__device__ float g_dhg[NM*N3];
__device__ float g_attn[NM*ND];
__device__ float g_p0[NM*ND];
__device__ float g_p1[NM*ND];
__device__ float g_p2[NM*ND];

#define BM 64
#define BN 64
#define BK 20        // 300 = 15 * 20; split-K3: 5 iters each
#define LPT 5        // loads/thread/tile: 64*20/256

typedef unsigned long long ull;

// ---------------- packed f32x2 helpers (FFMA2: 2x fp32 FMA rate) ------------
__device__ __forceinline__ ull pack2(float x, float y){
    ull r; asm("mov.b64 %0, {%1,%2};" : "=l"(r) : "f"(x), "f"(y)); return r;
}
__device__ __forceinline__ void ffma2(ull& d, ull a, ull b){
    asm("fma.rn.f32x2 %0, %1, %2, %0;" : "+l"(d) : "l"(a), "l"(b));
}
__device__ __forceinline__ float2 unpk(ull v){
    float2 r; asm("mov.b64 {%0,%1}, %2;" : "=f"(r.x), "=f"(r.y) : "l"(v)); return r;
}
__device__ __forceinline__ float ex2a(float x){ float y; asm("ex2.approx.f32 %0,%1;" : "=f"(y):"f"(x)); return y; }
__device__ __forceinline__ float rcpa(float x){ float y; asm("rcp.approx.f32 %0,%1;" : "=f"(y):"f"(x)); return y; }

// weight from precomputed pd=2^(dep'), ph=2^(head'): 4 instr, 2 MUFU
__device__ __forceinline__ float wfun2(float pd, float ph)
{
    float r = rcpa(fmaf(pd, ph, 1.f));
    return ex2a(K2 * r);
}

// 64x64 tile GEMM, C[m,n] += A[m,k]*W[n,k]. Double-buffered smem (R3/R5-proven).
__device__ __forceinline__ void gemm_core(const float* __restrict__ A,
                                          const float* __restrict__ W,
                                          int m0, int n0, int kstart, int niter,
                                          ull (&acc)[4][2])
{
    __shared__ __align__(16) float As[2][BK][BM+4];
    __shared__ __align__(16) float Bs[2][BK][BN+4];
    const int tid = threadIdx.x;
    const int tx = tid & 15, ty = tid >> 4;

    #pragma unroll
    for (int e = 0; e < LPT; ++e) {
        int idx = tid + e*256;
        int r = idx / BK, c = idx - r*BK;
        As[0][c][r] = A[(m0 + r)*NK + kstart + c];
        int gn = n0 + r;
        Bs[0][c][r] = (gn < ND) ? W[gn*NK + kstart + c] : 0.f;
    }
    __syncthreads();

    int buf = 0;
    for (int it = 0; it < niter; ++it) {
        const bool has_next = (it + 1 < niter);
        float ra[LPT], rb[LPT];
        if (has_next) {
            int kn = kstart + (it + 1)*BK;
            #pragma unroll
            for (int e = 0; e < LPT; ++e) {
                int idx = tid + e*256;
                int r = idx / BK, c = idx - r*BK;
                ra[e] = A[(m0 + r)*NK + kn + c];
                int gn = n0 + r;
                rb[e] = (gn < ND) ? W[gn*NK + kn + c] : 0.f;
            }
        }
        #pragma unroll
        for (int k = 0; k < BK; ++k) {
            const float4 af = *(const float4*)&As[buf][k][ty*4];
            const ull b0 = *(const ull*)&Bs[buf][k][tx*4];
            const ull b1 = *(const ull*)&Bs[buf][k][tx*4 + 2];
            ull a0 = pack2(af.x, af.x);
            ull a1 = pack2(af.y, af.y);
            ull a2 = pack2(af.z, af.z);
            ull a3 = pack2(af.w, af.w);
            ffma2(acc[0][0], a0, b0); ffma2(acc[0][1], a0, b1);
            ffma2(acc[1][0], a1, b0); ffma2(acc[1][1], a1, b1);
            ffma2(acc[2][0], a2, b0); ffma2(acc[2][1], a2, b1);
            ffma2(acc[3][0], a3, b0); ffma2(acc[3][1], a3, b1);
        }
        if (has_next) {
            __syncthreads();
            #pragma unroll
            for (int e = 0; e < LPT; ++e) {
                int idx = tid + e*256;
                int r = idx / BK, c = idx - r*BK;
                As[buf^1][c][r] = ra[e];
                Bs[buf^1][c][r] = rb[e];
            }
            __syncthreads();
            buf ^= 1;
        }
    }
}

__device__ __forceinline__ void store_partial(float* __restrict__ dst,
                                              ull (&acc)[4][2], int m0, int n0)
{
    const int tx = threadIdx.x & 15, ty = threadIdx.x >> 4;
    #pragma unroll
    for (int p = 0; p < 4; ++p) {
        int m = m0 + ty*4 + p;
        #pragma unroll
        for (int qq = 0; qq < 2; ++qq) {
            float2 v = unpk(acc[p][qq]);
            int n = n0 + tx*4 + qq*2;
            if (n < ND)     dst[m*ND + n]     = v.x;
            if (n + 1 < ND) dst[m*ND + n + 1] = v.y;
        }
    }
}

// ---- P1: rep partial GEMM, split-K3 (z: k in [100z, 100z+100), 5 iters) ----
__global__ void __launch_bounds__(256)
gemm_rep_split(const float* __restrict__ A, const float* __restrict__ W)
{
    const int m0 = blockIdx.y * BM, n0 = blockIdx.x * BN;
    const int z = blockIdx.z;
    float* __restrict__ dst = (z == 0) ? g_p0 : ((z == 1) ? g_p1 : g_p2);
    ull acc[4][2] = {};
    gemm_core(A, W, m0, n0, z*100, 5, acc);
    store_partial(dst, acc, m0, n0);
}

// ---- P1b: g_rep = elu(p0 + p1 + p2 + b_fc) ---------------------------------
__global__ void __launch_bounds__(256)
finish_rep(const float* __restrict__ bias)
{
    int idx = blockIdx.x * 256 + threadIdx.x;
    if (idx >= NM*ND) return;
    int n = idx % ND;
    float v = g_p0[idx] + g_p1[idx] + g_p2[idx] + bias[n];
    g_rep[idx] = (v > 0.f) ? v : expm1f(v);
}

// ---- P2: pd/ph/gate1 GEMM (z selects matrix; pd,ph stored as 2^(·K_PRE)) ---
__global__ void __launch_bounds__(256)
gemm_triple(const float* __restrict__ W1, const float* __restrict__ W2,
            const float* __restrict__ Wf1, const float* __restrict__ b1,
            const float* __restrict__ bf)
{
    const int m0 = blockIdx.y * BM, n0 = blockIdx.x * BN;
    const int z = blockIdx.z;
    const float* W = (z == 0) ? W1 : ((z == 1) ? W2 : Wf1);
    ull acc[4][2] = {};
    gemm_core(g_rep, W, m0, n0, 0, 15, acc);
    const int tx = threadIdx.x & 15, ty = threadIdx.x >> 4;
    #pragma unroll
    for (int p = 0; p < 4; ++p) {
        int m = m0 + ty*4 + p;
        #pragma unroll
        for (int qq = 0; qq < 2; ++qq) {
            float2 v = unpk(acc[p][qq]);
            int n = n0 + tx*4 + qq*2;
            #pragma unroll
            for (int h = 0; h < 2; ++h) {
                int nn = n + h;
                if (nn < ND) {
                    float val = (h == 0) ? v.x : v.y;
                    if (z == 0)      val = ex2a(val * K_PRE);              // pd
                    else if (z == 1) val = ex2a((val + b1[nn]) * K_PRE);   // ph
                    else             val += bf[nn];                        // g1
                    g_dhg[m*N3 + z*ND + nn] = val;
                }
            }
        }
    }
}

// ---- P3: attention (IG=2, j x4 pipelined; SWIZZLED bid->work for balance) --
// Flat grid of 512. b = bid&3; pair = (bid>>2)*53 mod 128. The 53-multiplier
// makes the 3-4 CTAs co-resident on one SM span the whole i-range, so per-SM
// total j-work is ~constant (kills the straggler tail).
__global__ void __launch_bounds__(320)
attn_kernel(const int* __restrict__ rmask)
{
    const int bid = blockIdx.x;
    const int b   = bid & 3;
    const int i0  = (((bid >> 2) * 53) & 127) * IG;
    const int t = threadIdx.x;

    __shared__ __align__(16) int2 joff[NS];   // (j*N3*4, j*ND*4) byte offsets
    __shared__ int wcnt[8];
    __shared__ int nvalid_s;
    __shared__ int jfirst_s;

    bool v = false;
    unsigned bal = 0;
    if (t < NS) {
        v = (t > i0) && (rmask[b*NS + t] != 0);
        bal = __ballot_sync(0xFFFFFFFFu, v);
        if ((t & 31) == 0) wcnt[t >> 5] = __popc(bal);
    }
    __syncthreads();
    if (t == 0) {
        int a = 0;
        #pragma unroll
        for (int k = 0; k < 8; ++k) { int c = wcnt[k]; wcnt[k] = a; a += c; }
        nvalid_s = a;
    }
    __syncthreads();
    if (t < NS && v) {
        int pos = wcnt[t >> 5] + __popc(bal & ((1u << (t & 31)) - 1u));
        joff[pos] = make_int2(t * (N3*4), t * (ND*4));
        if (pos == 0) jfirst_s = t;
    }
    __syncthreads();

    const int nvalid = nvalid_s;
    if (t >= ND) return;

    const float ph0 = g_dhg[(size_t)(b*NS + i0    )*N3 + ND + t];
    const float ph1 = g_dhg[(size_t)(b*NS + i0 + 1)*N3 + ND + t];
    const char* __restrict__ pdp = (const char*)(g_dhg + (size_t)(b*NS)*N3 + t);
    const char* __restrict__ rpp = (const char*)(g_rep + (size_t)(b*NS)*ND + t);

    float s0 = 0.f, w0 = 0.f, s1 = 0.f, w1 = 0.f;
    const int nvalid4 = nvalid & ~3;

    // software pipeline: group k+1's loads issued before group k's compute uses
    float pdc[4], rvc[4];
    if (nvalid4 > 0) {
        const int4 oa = *(const int4*)&joff[0];
        const int4 ob = *(const int4*)&joff[2];
        pdc[0] = *(const float*)(pdp + oa.x);
        pdc[1] = *(const float*)(pdp + oa.z);
        pdc[2] = *(const float*)(pdp + ob.x);
        pdc[3] = *(const float*)(pdp + ob.z);
        rvc[0] = *(const float*)(rpp + oa.y);
        rvc[1] = *(const float*)(rpp + oa.w);
        rvc[2] = *(const float*)(rpp + ob.y);
        rvc[3] = *(const float*)(rpp + ob.w);
    }
    for (int idx = 0; idx < nvalid4; idx += 4) {
        float pdn[4], rvn[4];
        const bool hn = (idx + 4) < nvalid4;
        if (hn) {
            const int4 oa = *(const int4*)&joff[idx + 4];
            const int4 ob = *(const int4*)&joff[idx + 6];
            pdn[0] = *(const float*)(pdp + oa.x);
            pdn[1] = *(const float*)(pdp + oa.z);
            pdn[2] = *(const float*)(pdp + ob.x);
            pdn[3] = *(const float*)(pdp + ob.z);
            rvn[0] = *(const float*)(rpp + oa.y);
            rvn[1] = *(const float*)(rpp + oa.w);
            rvn[2] = *(const float*)(rpp + ob.y);
            rvn[3] = *(const float*)(rpp + ob.w);
        }
        float e00 = wfun2(pdc[0], ph0), e10 = wfun2(pdc[0], ph1);
        float e01 = wfun2(pdc[1], ph0), e11 = wfun2(pdc[1], ph1);
        float e02 = wfun2(pdc[2], ph0), e12 = wfun2(pdc[2], ph1);
        float e03 = wfun2(pdc[3], ph0), e13 = wfun2(pdc[3], ph1);
        s0 += (e00 + e01) + (e02 + e03);
        s1 += (e10 + e11) + (e12 + e13);
        w0 = fmaf(e00, rvc[0], fmaf(e01, rvc[1], fmaf(e02, rvc[2], fmaf(e03, rvc[3], w0))));
        w1 = fmaf(e10, rvc[0], fmaf(e11, rvc[1], fmaf(e12, rvc[2], fmaf(e13, rvc[3], w1))));
        if (hn) {
            #pragma unroll
            for (int q = 0; q < 4; ++q) { pdc[q] = pdn[q]; rvc[q] = rvn[q]; }
        }
    }
    for (int idx = nvalid4; idx < nvalid; ++idx) {
        const int2 o = joff[idx];
        float pd = *(const float*)(pdp + o.x);
        float rv = *(const float*)(rpp + o.y);
        float e0 = wfun2(pd, ph0), e1 = wfun2(pd, ph1);
        s0 += e0;  w0 = fmaf(e0, rv, w0);
        s1 += e1;  w1 = fmaf(e1, rv, w1);
    }
    // i1 = i0+1 must exclude j == i0+1 (only possibly-invalid entry = first);
    // exact cancellation: identical op sequence both times.
    if (nvalid > 0 && jfirst_s == i0 + 1) {
        float pd = *(const float*)(pdp + (i0 + 1)*(N3*4));
        float rv = *(const float*)(rpp + (i0 + 1)*(ND*4));
        float e1 = wfun2(pd, ph1);
        s1 -= e1;  w1 = fmaf(-e1, rv, w1);
    }
    float d0 = s0 + ((s0 == 0.f) ? 1.f : 0.f) + 1e-20f;
    float d1 = s1 + ((s1 == 0.f) ? 1.f : 0.f) + 1e-20f;
    g_attn[(size_t)(b*NS + i0    )*ND + t] = __fdividef(w0, d0);
    g_attn[(size_t)(b*NS + i0 + 1)*ND + t] = __fdividef(w1, d1);
}

// ---- P4: attn @ W_f2^T, split-K3 partials ----------------------------------
__global__ void __launch_bounds__(256)
gemm_final_split(const float* __restrict__ Wf2)
{
    const int m0 = blockIdx.y * BM, n0 = blockIdx.x * BN;
    const int z = blockIdx.z;
    float* __restrict__ dst = (z == 0) ? g_p0 : ((z == 1) ? g_p1 : g_p2);
    ull acc[4][2] = {};
    gemm_core(g_attn, Wf2, m0, n0, z*100, 5, acc);
    store_partial(dst, acc, m0, n0);
}

// ---- P4b: gate + blend + mask ----------------------------------------------
__global__ void __launch_bounds__(256)
final_epi(const int* __restrict__ rmask, float* __restrict__ out)
{
    int idx = blockIdx.x * 256 + threadIdx.x;
    if (idx >= NM*ND) return;
    int m = idx / ND, n = idx - m*ND;
    float vv = g_p0[idx] + g_p1[idx] + g_p2[idx] + g_dhg[m*N3 + 2*ND + n];
    float gate = rcpa(1.f + ex2a(-vv * LOG2E));
    float r = g_rep[idx];
    float a = g_attn[idx];
    out[idx] = (gate*r + (1.f - gate)*a) * (float)rmask[m];
}

extern "C" void kernel_launch(void* const* d_in, const int* in_sizes, int n_in,
                              void* d_out, int out_size)
{
    const float* inputs = (const float*)d_in[0];
    const int*   rmask  = (const int*)d_in[1];
    const float* W_fc   = (const float*)d_in[2];
    const float* b_fc   = (const float*)d_in[3];
    const float* W1     = (const float*)d_in[4];
    const float* W2     = (const float*)d_in[5];
    const float* b1     = (const float*)d_in[6];
    const float* W_f1   = (const float*)d_in[7];
    const float* W_f2   = (const float*)d_in[8];
    const float* b_f    = (const float*)d_in[9];
    float* out = (float*)d_out;

    dim3 blk(256);
    const int eBlocks = (NM*ND + 255) / 256;

    gemm_rep_split  <<<dim3(5, 16, 3), blk>>>(inputs, W_fc);
    finish_rep      <<<eBlocks, blk>>>(b_fc);
    gemm_triple     <<<dim3(5, 16, 3), blk>>>(W1, W2, W_f1, b1, b_f);
    attn_kernel     <<<(NS/IG)*NB, 320>>>(rmask);
    gemm_final_split<<<dim3(5, 16, 3), blk>>>(W_f2);
    final_epi       <<<eBlocks, blk>>>(rmask, out);
}

// round 14
// speedup vs baseline: 1.1983x; 1.1135x over previous
#include <cuda_runtime.h>
#include <math.h>

#define NB 4
#define NS 256
#define ND 300
#define NM (NB*NS)   // 1024 rows
#define NK 300
#define N3 (3*ND)    // 900: pd | ph | g1(+b_f)
#define CC 5.0f
#define IG 2

// weight: exp(C*tanh(x/C)) = e^C * 2^(K2/(1 + 2^(x*K_PRE))); e^C cancels in softmax
#define K_PRE 0.5770780163555854f     //  2*log2(e)/C
#define K2   -14.426950408889634f     // -2*C*log2(e)
#define LOG2E 1.4426950408889634f

// Scratch (static device globals — no allocation allowed)
__device__ float g_rep[NM*ND];
__device__ float g_dhg[NM*N3];
__device__ float g_attn[NM*ND];
__device__ float g_p0[NM*ND];
__device__ float g_p1[NM*ND];
__device__ float g_p2[NM*ND];

#define BM 64
#define BN 64
#define BK 20        // 300 = 15 * 20; split-K3: 5 iters each
#define LPT 5        // loads/thread/tile: 64*20/256

typedef unsigned long long ull;

// ---------------- packed f32x2 helpers (FFMA2: 2x fp32 FMA rate) ------------
__device__ __forceinline__ ull pack2(float x, float y){
    ull r; asm("mov.b64 %0, {%1,%2};" : "=l"(r) : "f"(x), "f"(y)); return r;
}
__device__ __forceinline__ void ffma2(ull& d, ull a, ull b){
    asm("fma.rn.f32x2 %0, %1, %2, %0;" : "+l"(d) : "l"(a), "l"(b));
}
__device__ __forceinline__ float2 unpk(ull v){
    float2 r; asm("mov.b64 {%0,%1}, %2;" : "=f"(r.x), "=f"(r.y) : "l"(v)); return r;
}
__device__ __forceinline__ float ex2a(float x){ float y; asm("ex2.approx.f32 %0,%1;" : "=f"(y):"f"(x)); return y; }
__device__ __forceinline__ float rcpa(float x){ float y; asm("rcp.approx.f32 %0,%1;" : "=f"(y):"f"(x)); return y; }

// weight from precomputed pd=2^(dep'), ph=2^(head'): 4 instr, 2 MUFU
__device__ __forceinline__ float wfun2(float pd, float ph)
{
    float r = rcpa(fmaf(pd, ph, 1.f));
    return ex2a(K2 * r);
}

// 64x64 tile GEMM, C[m,n] += A[m,k]*W[n,k]. Double-buffered smem (R3/R5-proven).
__device__ __forceinline__ void gemm_core(const float* __restrict__ A,
                                          const float* __restrict__ W,
                                          int m0, int n0, int kstart, int niter,
                                          ull (&acc)[4][2])
{
    __shared__ __align__(16) float As[2][BK][BM+4];
    __shared__ __align__(16) float Bs[2][BK][BN+4];
    const int tid = threadIdx.x;
    const int tx = tid & 15, ty = tid >> 4;

    #pragma unroll
    for (int e = 0; e < LPT; ++e) {
        int idx = tid + e*256;
        int r = idx / BK, c = idx - r*BK;
        As[0][c][r] = A[(m0 + r)*NK + kstart + c];
        int gn = n0 + r;
        Bs[0][c][r] = (gn < ND) ? W[gn*NK + kstart + c] : 0.f;
    }
    __syncthreads();

    int buf = 0;
    for (int it = 0; it < niter; ++it) {
        const bool has_next = (it + 1 < niter);
        float ra[LPT], rb[LPT];
        if (has_next) {
            int kn = kstart + (it + 1)*BK;
            #pragma unroll
            for (int e = 0; e < LPT; ++e) {
                int idx = tid + e*256;
                int r = idx / BK, c = idx - r*BK;
                ra[e] = A[(m0 + r)*NK + kn + c];
                int gn = n0 + r;
                rb[e] = (gn < ND) ? W[gn*NK + kn + c] : 0.f;
            }
        }
        #pragma unroll
        for (int k = 0; k < BK; ++k) {
            const float4 af = *(const float4*)&As[buf][k][ty*4];
            const ull b0 = *(const ull*)&Bs[buf][k][tx*4];
            const ull b1 = *(const ull*)&Bs[buf][k][tx*4 + 2];
            ull a0 = pack2(af.x, af.x);
            ull a1 = pack2(af.y, af.y);
            ull a2 = pack2(af.z, af.z);
            ull a3 = pack2(af.w, af.w);
            ffma2(acc[0][0], a0, b0); ffma2(acc[0][1], a0, b1);
            ffma2(acc[1][0], a1, b0); ffma2(acc[1][1], a1, b1);
            ffma2(acc[2][0], a2, b0); ffma2(acc[2][1], a2, b1);
            ffma2(acc[3][0], a3, b0); ffma2(acc[3][1], a3, b1);
        }
        if (has_next) {
            __syncthreads();
            #pragma unroll
            for (int e = 0; e < LPT; ++e) {
                int idx = tid + e*256;
                int r = idx / BK, c = idx - r*BK;
                As[buf^1][c][r] = ra[e];
                Bs[buf^1][c][r] = rb[e];
            }
            __syncthreads();
            buf ^= 1;
        }
    }
}

__device__ __forceinline__ void store_partial(float* __restrict__ dst,
                                              ull (&acc)[4][2], int m0, int n0)
{
    const int tx = threadIdx.x & 15, ty = threadIdx.x >> 4;
    #pragma unroll
    for (int p = 0; p < 4; ++p) {
        int m = m0 + ty*4 + p;
        #pragma unroll
        for (int qq = 0; qq < 2; ++qq) {
            float2 v = unpk(acc[p][qq]);
            int n = n0 + tx*4 + qq*2;
            if (n < ND)     dst[m*ND + n]     = v.x;
            if (n + 1 < ND) dst[m*ND + n + 1] = v.y;
        }
    }
}

// ---- P1: rep partial GEMM, split-K3 (z: k in [100z, 100z+100), 5 iters) ----
__global__ void __launch_bounds__(256)
gemm_rep_split(const float* __restrict__ A, const float* __restrict__ W)
{
    const int m0 = blockIdx.y * BM, n0 = blockIdx.x * BN;
    const int z = blockIdx.z;
    float* __restrict__ dst = (z == 0) ? g_p0 : ((z == 1) ? g_p1 : g_p2);
    ull acc[4][2] = {};
    gemm_core(A, W, m0, n0, z*100, 5, acc);
    store_partial(dst, acc, m0, n0);
}

// ---- P1b: g_rep = elu(p0 + p1 + p2 + b_fc) ---------------------------------
__global__ void __launch_bounds__(256)
finish_rep(const float* __restrict__ bias)
{
    int idx = blockIdx.x * 256 + threadIdx.x;
    if (idx >= NM*ND) return;
    int n = idx % ND;
    float v = g_p0[idx] + g_p1[idx] + g_p2[idx] + bias[n];
    g_rep[idx] = (v > 0.f) ? v : expm1f(v);
}

// ---- P2: pd/ph/gate1 GEMM (z selects matrix; pd,ph stored as 2^(·K_PRE)) ---
__global__ void __launch_bounds__(256)
gemm_triple(const float* __restrict__ W1, const float* __restrict__ W2,
            const float* __restrict__ Wf1, const float* __restrict__ b1,
            const float* __restrict__ bf)
{
    const int m0 = blockIdx.y * BM, n0 = blockIdx.x * BN;
    const int z = blockIdx.z;
    const float* W = (z == 0) ? W1 : ((z == 1) ? W2 : Wf1);
    ull acc[4][2] = {};
    gemm_core(g_rep, W, m0, n0, 0, 15, acc);
    const int tx = threadIdx.x & 15, ty = threadIdx.x >> 4;
    #pragma unroll
    for (int p = 0; p < 4; ++p) {
        int m = m0 + ty*4 + p;
        #pragma unroll
        for (int qq = 0; qq < 2; ++qq) {
            float2 v = unpk(acc[p][qq]);
            int n = n0 + tx*4 + qq*2;
            #pragma unroll
            for (int h = 0; h < 2; ++h) {
                int nn = n + h;
                if (nn < ND) {
                    float val = (h == 0) ? v.x : v.y;
                    if (z == 0)      val = ex2a(val * K_PRE);              // pd
                    else if (z == 1) val = ex2a((val + b1[nn]) * K_PRE);   // ph
                    else             val += bf[nn];                        // g1
                    g_dhg[m*N3 + z*ND + nn] = val;
                }
            }
        }
    }
}

// macro: load 4-j group g (pd, rv) from byte-offset list
#define LOAD_GROUP(g, pd_, rv_) do {                        \
    const int4 oa = *(const int4*)&joff[(g)*4];             \
    const int4 ob = *(const int4*)&joff[(g)*4 + 2];         \
    pd_[0] = *(const float*)(pdp + oa.x);                   \
    pd_[1] = *(const float*)(pdp + oa.z);                   \
    pd_[2] = *(const float*)(pdp + ob.x);                   \
    pd_[3] = *(const float*)(pdp + ob.z);                   \
    rv_[0] = *(const float*)(rpp + oa.y);                   \
    rv_[1] = *(const float*)(rpp + oa.w);                   \
    rv_[2] = *(const float*)(rpp + ob.y);                   \
    rv_[3] = *(const float*)(rpp + ob.w);                   \
} while (0)

// ---- P3: attention (IG=2, byte-offset list, j x4, depth-2 sw pipeline) -----
__global__ void __launch_bounds__(320, 3)
attn_kernel(const int* __restrict__ rmask)
{
    const int b = blockIdx.y;
    const int i0 = blockIdx.x * IG;
    const int t = threadIdx.x;

    __shared__ __align__(16) int2 joff[NS];   // (j*N3*4, j*ND*4) byte offsets
    __shared__ int wcnt[8];
    __shared__ int nvalid_s;
    __shared__ int jfirst_s;

    bool v = false;
    unsigned bal = 0;
    if (t < NS) {
        v = (t > i0) && (rmask[b*NS + t] != 0);
        bal = __ballot_sync(0xFFFFFFFFu, v);
        if ((t & 31) == 0) wcnt[t >> 5] = __popc(bal);
    }
    __syncthreads();
    if (t == 0) {
        int a = 0;
        #pragma unroll
        for (int k = 0; k < 8; ++k) { int c = wcnt[k]; wcnt[k] = a; a += c; }
        nvalid_s = a;
    }
    __syncthreads();
    if (t < NS && v) {
        int pos = wcnt[t >> 5] + __popc(bal & ((1u << (t & 31)) - 1u));
        joff[pos] = make_int2(t * (N3*4), t * (ND*4));
        if (pos == 0) jfirst_s = t;
    }
    __syncthreads();

    const int nvalid = nvalid_s;
    if (t >= ND) return;

    const float ph0 = g_dhg[(size_t)(b*NS + i0    )*N3 + ND + t];
    const float ph1 = g_dhg[(size_t)(b*NS + i0 + 1)*N3 + ND + t];
    const char* __restrict__ pdp = (const char*)(g_dhg + (size_t)(b*NS)*N3 + t);
    const char* __restrict__ rpp = (const char*)(g_rep + (size_t)(b*NS)*ND + t);

    float s0 = 0.f, w0 = 0.f, s1 = 0.f, w1 = 0.f;
    const int G = (nvalid & ~3) >> 2;   // number of full 4-j groups

    // depth-2 software pipeline: groups g+1, g+2 in flight while computing g
    float pdA[4], rvA[4], pdB[4], rvB[4];
    if (G > 0) LOAD_GROUP(0, pdA, rvA);
    if (G > 1) LOAD_GROUP(1, pdB, rvB);
    for (int g = 0; g < G; ++g) {
        float pdC[4], rvC[4];
        if (g + 2 < G) LOAD_GROUP(g + 2, pdC, rvC);
        float e00 = wfun2(pdA[0], ph0), e10 = wfun2(pdA[0], ph1);
        float e01 = wfun2(pdA[1], ph0), e11 = wfun2(pdA[1], ph1);
        float e02 = wfun2(pdA[2], ph0), e12 = wfun2(pdA[2], ph1);
        float e03 = wfun2(pdA[3], ph0), e13 = wfun2(pdA[3], ph1);
        s0 += (e00 + e01) + (e02 + e03);
        s1 += (e10 + e11) + (e12 + e13);
        w0 = fmaf(e00, rvA[0], fmaf(e01, rvA[1], fmaf(e02, rvA[2], fmaf(e03, rvA[3], w0))));
        w1 = fmaf(e10, rvA[0], fmaf(e11, rvA[1], fmaf(e12, rvA[2], fmaf(e13, rvA[3], w1))));
        #pragma unroll
        for (int q = 0; q < 4; ++q) {
            pdA[q] = pdB[q]; rvA[q] = rvB[q];
            pdB[q] = pdC[q]; rvB[q] = rvC[q];
        }
    }
    for (int idx = G*4; idx < nvalid; ++idx) {
        const int2 o = joff[idx];
        float pd = *(const float*)(pdp + o.x);
        float rv = *(const float*)(rpp + o.y);
        float e0 = wfun2(pd, ph0), e1 = wfun2(pd, ph1);
        s0 += e0;  w0 = fmaf(e0, rv, w0);
        s1 += e1;  w1 = fmaf(e1, rv, w1);
    }
    // i1 = i0+1 must exclude j == i0+1 (only possibly-invalid entry = first);
    // exact cancellation: identical op sequence both times.
    if (nvalid > 0 && jfirst_s == i0 + 1) {
        float pd = *(const float*)(pdp + (i0 + 1)*(N3*4));
        float rv = *(const float*)(rpp + (i0 + 1)*(ND*4));
        float e1 = wfun2(pd, ph1);
        s1 -= e1;  w1 = fmaf(-e1, rv, w1);
    }
    float d0 = s0 + ((s0 == 0.f) ? 1.f : 0.f) + 1e-20f;
    float d1 = s1 + ((s1 == 0.f) ? 1.f : 0.f) + 1e-20f;
    g_attn[(size_t)(b*NS + i0    )*ND + t] = __fdividef(w0, d0);
    g_attn[(size_t)(b*NS + i0 + 1)*ND + t] = __fdividef(w1, d1);
}

// ---- P4: attn @ W_f2^T, split-K3 partials ----------------------------------
__global__ void __launch_bounds__(256)
gemm_final_split(const float* __restrict__ Wf2)
{
    const int m0 = blockIdx.y * BM, n0 = blockIdx.x * BN;
    const int z = blockIdx.z;
    float* __restrict__ dst = (z == 0) ? g_p0 : ((z == 1) ? g_p1 : g_p2);
    ull acc[4][2] = {};
    gemm_core(g_attn, Wf2, m0, n0, z*100, 5, acc);
    store_partial(dst, acc, m0, n0);
}

// ---- P4b: gate + blend + mask ----------------------------------------------
__global__ void __launch_bounds__(256)
final_epi(const int* __restrict__ rmask, float* __restrict__ out)
{
    int idx = blockIdx.x * 256 + threadIdx.x;
    if (idx >= NM*ND) return;
    int m = idx / ND, n = idx - m*ND;
    float vv = g_p0[idx] + g_p1[idx] + g_p2[idx] + g_dhg[m*N3 + 2*ND + n];
    float gate = rcpa(1.f + ex2a(-vv * LOG2E));
    float r = g_rep[idx];
    float a = g_attn[idx];
    out[idx] = (gate*r + (1.f - gate)*a) * (float)rmask[m];
}

extern "C" void kernel_launch(void* const* d_in, const int* in_sizes, int n_in,
                              void* d_out, int out_size)
{
    const float* inputs = (const float*)d_in[0];
    const int*   rmask  = (const int*)d_in[1];
    const float* W_fc   = (const float*)d_in[2];
    const float* b_fc   = (const float*)d_in[3];
    const float* W1     = (const float*)d_in[4];
    const float* W2     = (const float*)d_in[5];
    const float* b1     = (const float*)d_in[6];
    const float* W_f1   = (const float*)d_in[7];
    const float* W_f2   = (const float*)d_in[8];
    const float* b_f    = (const float*)d_in[9];
    float* out = (float*)d_out;

    dim3 blk(256);
    const int eBlocks = (NM*ND + 255) / 256;

    gemm_rep_split  <<<dim3(5, 16, 3), blk>>>(inputs, W_fc);
    finish_rep      <<<eBlocks, blk>>>(b_fc);
    gemm_triple     <<<dim3(5, 16, 3), blk>>>(W1, W2, W_f1, b1, b_f);
    attn_kernel     <<<dim3(NS/IG, NB), 320>>>(rmask);
    gemm_final_split<<<dim3(5, 16, 3), blk>>>(W_f2);
    final_epi       <<<eBlocks, blk>>>(rmask, out);
}